// round 1
// baseline (speedup 1.0000x reference)
#include <cuda_runtime.h>
#include <cstdint>

typedef unsigned long long ull;

#define DEV_INLINE __device__ __forceinline__

DEV_INLINE ull pack2(float lo, float hi) {
    ull r; asm("mov.b64 %0,{%1,%2};" : "=l"(r) : "f"(lo), "f"(hi)); return r;
}
DEV_INLINE void unpack2(ull v, float& lo, float& hi) {
    asm("mov.b64 {%0,%1},%2;" : "=f"(lo), "=f"(hi) : "l"(v));
}
DEV_INLINE ull fma2(ull a, ull b, ull c) {
    ull d; asm("fma.rn.f32x2 %0,%1,%2,%3;" : "=l"(d) : "l"(a), "l"(b), "l"(c)); return d;
}
DEV_INLINE ull mul2(ull a, ull b) {
    ull d; asm("mul.rn.f32x2 %0,%1,%2;" : "=l"(d) : "l"(a), "l"(b)); return d;
}

constexpr int B  = 4;
constexpr int C  = 64;
constexpr int CK = 8;
constexpr int N  = 4096;
constexpr int TQ = 64;   // queries per block
constexpr int TK = 64;   // keys per tile
constexpr int NT = N / TK;

// Scratch (device globals: allocation-guard safe)
__device__ float g_q[B * CK * N];
__device__ float g_k[B * CK * N];
__device__ float g_v[B * C * N];

// ---------------------------------------------------------------------------
// QKV projection: q/k/v[b][o][n] = sum_c w[o][c] * x[b][c][n] + bias[o]
// grid = 64 blocks (4 batches x 16 n-chunks of 256), 256 threads, 1 n/thread
// ---------------------------------------------------------------------------
__global__ __launch_bounds__(256, 1) void qkv_kernel(
    const float* __restrict__ x,
    const float* __restrict__ wq, const float* __restrict__ bq,
    const float* __restrict__ wk, const float* __restrict__ bk,
    const float* __restrict__ wv, const float* __restrict__ bv)
{
    __shared__ float s_wq[CK * C], s_wk[CK * C], s_wv[C * C];
    __shared__ float s_b[2 * CK + C];
    int tid = threadIdx.x;
    for (int i = tid; i < CK * C; i += 256) { s_wq[i] = wq[i]; s_wk[i] = wk[i]; }
    for (int i = tid; i < C * C; i += 256) s_wv[i] = wv[i];
    if (tid < CK) s_b[tid] = bq[tid];
    else if (tid < 2 * CK) s_b[tid] = bk[tid - CK];
    else if (tid < 2 * CK + C) s_b[tid] = bv[tid - 2 * CK];
    __syncthreads();

    int b = blockIdx.x >> 4;
    int n = ((blockIdx.x & 15) << 8) + tid;
    const float* xb = x + (size_t)b * C * N + n;

    // Phase 1: q, k  (16 accumulators)
    float aq[CK], ak[CK];
#pragma unroll
    for (int o = 0; o < CK; o++) { aq[o] = 0.f; ak[o] = 0.f; }
    for (int c = 0; c < C; c++) {
        float xc = xb[(size_t)c * N];
#pragma unroll
        for (int o = 0; o < CK; o++) {
            aq[o] += s_wq[o * C + c] * xc;
            ak[o] += s_wk[o * C + c] * xc;
        }
    }
#pragma unroll
    for (int o = 0; o < CK; o++) {
        g_q[(b * CK + o) * N + n] = aq[o] + s_b[o];
        g_k[(b * CK + o) * N + n] = ak[o] + s_b[CK + o];
    }

    // Phase 2: v (64 accumulators, x re-read hits L1/L2)
    float av[C];
#pragma unroll
    for (int o = 0; o < C; o++) av[o] = 0.f;
    for (int c = 0; c < C; c++) {
        float xc = xb[(size_t)c * N];
#pragma unroll
        for (int o = 0; o < C; o++) av[o] += s_wv[o * C + c] * xc;
    }
#pragma unroll
    for (int o = 0; o < C; o++) g_v[(b * C + o) * N + n] = av[o] + s_b[2 * CK + o];
}

// ---------------------------------------------------------------------------
// Flash attention: grid (N/TQ, B), 256 threads = 64 queries x 4 channel-groups.
// Thread (qi, cg): owns query qi, v-channels c = 4h+cg (h=0..15).
// Scores/exp split across the quad (cg owns j in [cg*16, cg*16+16)),
// probabilities broadcast via shfl. Packed f32x2 FMA throughout.
// ---------------------------------------------------------------------------
__global__ __launch_bounds__(256, 1) void attn_kernel(
    const float* __restrict__ x,
    const float* __restrict__ gamma_p,
    float* __restrict__ out)
{
    __shared__ __align__(16) float k_s[CK][TK];   // [kk][j]
    __shared__ __align__(16) float v_s[C][68];    // [c][j], pad 68 -> conflict-free reads

    int tid = threadIdx.x;
    int qi = tid >> 2, cg = tid & 3;
    int b = blockIdx.y;
    int qglob = blockIdx.x * TQ + qi;
    int lane = tid & 31;
    int quadbase = lane & ~3;

    // Load + pre-pack q (constant across tiles)
    ull q2[CK];
#pragma unroll
    for (int kk = 0; kk < CK; kk++) {
        float qv = g_q[(b * CK + kk) * N + qglob];
        q2[kk] = pack2(qv, qv);
    }

    float m = -3.0e38f, l = 0.f;
    ull acc[16];   // f32x2 partial sums (even-j / odd-j), per owned channel
#pragma unroll
    for (int h = 0; h < 16; h++) acc[h] = 0ull;

    for (int kt = 0; kt < NT; kt++) {
        int j0 = kt * TK;
        __syncthreads();
        // Cooperative tile loads (gmem-coalesced, STS conflict-free)
        for (int idx = tid; idx < CK * TK; idx += 256) {
            int kk = idx >> 6, j = idx & 63;
            k_s[kk][j] = g_k[(b * CK + kk) * N + j0 + j];
        }
        for (int idx = tid; idx < C * TK; idx += 256) {
            int c = idx >> 6, j = idx & 63;
            v_s[c][j] = g_v[(b * C + c) * N + j0 + j];
        }
        __syncthreads();

        // Scores for own 16 j's (j = cg*16 + jj), packed over j-pairs
        ull s2[8];
#pragma unroll
        for (int p = 0; p < 8; p++) s2[p] = 0ull;
#pragma unroll
        for (int kk = 0; kk < CK; kk++) {
            const ull* krow = (const ull*)&k_s[kk][cg * 16];
#pragma unroll
            for (int p = 0; p < 8; p++) s2[p] = fma2(krow[p], q2[kk], s2[p]);
        }
        float s[16];
#pragma unroll
        for (int p = 0; p < 8; p++) unpack2(s2[p], s[2 * p], s[2 * p + 1]);

        // Online softmax bookkeeping (quad reduction -> identical on all 4 lanes)
        float tmax = s[0];
#pragma unroll
        for (int jj = 1; jj < 16; jj++) tmax = fmaxf(tmax, s[jj]);
        tmax = fmaxf(tmax, __shfl_xor_sync(0xffffffffu, tmax, 1));
        tmax = fmaxf(tmax, __shfl_xor_sync(0xffffffffu, tmax, 2));
        float m_new = fmaxf(m, tmax);
        float alpha = __expf(m - m_new);

        float p_l[16];
        float lsum = 0.f;
#pragma unroll
        for (int jj = 0; jj < 16; jj++) {
            p_l[jj] = __expf(s[jj] - m_new);
            lsum += p_l[jj];
        }
        lsum += __shfl_xor_sync(0xffffffffu, lsum, 1);
        lsum += __shfl_xor_sync(0xffffffffu, lsum, 2);
        l = l * alpha + lsum;
        m = m_new;

        ull alpha2 = pack2(alpha, alpha);
#pragma unroll
        for (int h = 0; h < 16; h++) acc[h] = mul2(acc[h], alpha2);

        // Accumulate PV over all 64 j; p broadcast from quad lane owning that j16 block
#pragma unroll
        for (int jt = 0; jt < 4; jt++) {
            int src = quadbase + jt;
#pragma unroll
            for (int pq = 0; pq < 4; pq++) {
                float p0 = __shfl_sync(0xffffffffu, p_l[pq * 4 + 0], src);
                float p1 = __shfl_sync(0xffffffffu, p_l[pq * 4 + 1], src);
                float p2 = __shfl_sync(0xffffffffu, p_l[pq * 4 + 2], src);
                float p3 = __shfl_sync(0xffffffffu, p_l[pq * 4 + 3], src);
                ull pj01 = pack2(p0, p1);
                ull pj23 = pack2(p2, p3);
                int j4 = jt * 16 + pq * 4;
#pragma unroll
                for (int h = 0; h < 16; h++) {
                    int c = 4 * h + cg;
                    ulonglong2 v2 = *(const ulonglong2*)&v_s[c][j4];
                    acc[h] = fma2(v2.x, pj01, acc[h]);
                    acc[h] = fma2(v2.y, pj23, acc[h]);
                }
            }
        }
    }

    // Epilogue: out = gamma * (acc/l) + x
    float inv_l = 1.f / l;
    float gamma = gamma_p[0];
#pragma unroll
    for (int h = 0; h < 16; h++) {
        float lo, hi;
        unpack2(acc[h], lo, hi);
        float a = (lo + hi) * inv_l;
        int c = 4 * h + cg;
        size_t oidx = (size_t)(b * C + c) * N + qglob;
        out[oidx] = gamma * a + x[oidx];
    }
}

// ---------------------------------------------------------------------------
extern "C" void kernel_launch(void* const* d_in, const int* in_sizes, int n_in,
                              void* d_out, int out_size)
{
    const float* x     = (const float*)d_in[0];
    const float* wq    = (const float*)d_in[1];
    const float* bq    = (const float*)d_in[2];
    const float* wk    = (const float*)d_in[3];
    const float* bk    = (const float*)d_in[4];
    const float* wv    = (const float*)d_in[5];
    const float* bv    = (const float*)d_in[6];
    const float* gamma = (const float*)d_in[7];
    float* out = (float*)d_out;

    qkv_kernel<<<64, 256>>>(x, wq, bq, wk, bk, wv, bv);
    dim3 grid(N / TQ, B);
    attn_kernel<<<grid, 256>>>(x, gamma, out);
}

// round 3
// speedup vs baseline: 1.1641x; 1.1641x over previous
#include <cuda_runtime.h>
#include <cstdint>

typedef unsigned long long ull;

#define DEV_INLINE __device__ __forceinline__

DEV_INLINE ull pack2(float lo, float hi) {
    ull r; asm("mov.b64 %0,{%1,%2};" : "=l"(r) : "f"(lo), "f"(hi)); return r;
}
DEV_INLINE void unpack2(ull v, float& lo, float& hi) {
    asm("mov.b64 {%0,%1},%2;" : "=f"(lo), "=f"(hi) : "l"(v));
}
DEV_INLINE ull fma2(ull a, ull b, ull c) {
    ull d; asm("fma.rn.f32x2 %0,%1,%2,%3;" : "=l"(d) : "l"(a), "l"(b), "l"(c)); return d;
}
DEV_INLINE ull mul2(ull a, ull b) {
    ull d; asm("mul.rn.f32x2 %0,%1,%2;" : "=l"(d) : "l"(a), "l"(b)); return d;
}

constexpr int B  = 4;
constexpr int C  = 64;
constexpr int CK = 8;
constexpr int N  = 4096;
constexpr int TQ = 64;   // queries per block
constexpr int TK = 64;   // keys per tile
constexpr int NT = N / TK;

// Scratch (device globals: allocation-guard safe)
__device__ float g_q[B * CK * N];
__device__ float g_k[B * CK * N];
__device__ float g_v[B * C * N];

// ---------------------------------------------------------------------------
// QKV projection: q/k/v[b][o][n] = sum_c w[o][c] * x[b][c][n] + bias[o]
// ---------------------------------------------------------------------------
__global__ __launch_bounds__(256, 1) void qkv_kernel(
    const float* __restrict__ x,
    const float* __restrict__ wq, const float* __restrict__ bq,
    const float* __restrict__ wk, const float* __restrict__ bk,
    const float* __restrict__ wv, const float* __restrict__ bv)
{
    __shared__ float s_wq[CK * C], s_wk[CK * C], s_wv[C * C];
    __shared__ float s_b[2 * CK + C];
    int tid = threadIdx.x;
    for (int i = tid; i < CK * C; i += 256) { s_wq[i] = wq[i]; s_wk[i] = wk[i]; }
    for (int i = tid; i < C * C; i += 256) s_wv[i] = wv[i];
    if (tid < CK) s_b[tid] = bq[tid];
    else if (tid < 2 * CK) s_b[tid] = bk[tid - CK];
    else if (tid < 2 * CK + C) s_b[tid] = bv[tid - 2 * CK];
    __syncthreads();

    int b = blockIdx.x >> 4;
    int n = ((blockIdx.x & 15) << 8) + tid;
    const float* xb = x + (size_t)b * C * N + n;

    float aq[CK], ak[CK];
#pragma unroll
    for (int o = 0; o < CK; o++) { aq[o] = 0.f; ak[o] = 0.f; }
    for (int c = 0; c < C; c++) {
        float xc = xb[(size_t)c * N];
#pragma unroll
        for (int o = 0; o < CK; o++) {
            aq[o] += s_wq[o * C + c] * xc;
            ak[o] += s_wk[o * C + c] * xc;
        }
    }
#pragma unroll
    for (int o = 0; o < CK; o++) {
        g_q[(b * CK + o) * N + n] = aq[o] + s_b[o];
        g_k[(b * CK + o) * N + n] = ak[o] + s_b[CK + o];
    }

    float av[C];
#pragma unroll
    for (int o = 0; o < C; o++) av[o] = 0.f;
    for (int c = 0; c < C; c++) {
        float xc = xb[(size_t)c * N];
#pragma unroll
        for (int o = 0; o < C; o++) av[o] += s_wv[o * C + c] * xc;
    }
#pragma unroll
    for (int o = 0; o < C; o++) g_v[(b * C + o) * N + n] = av[o] + s_b[2 * CK + o];
}

// ---------------------------------------------------------------------------
// Flash attention: grid (N/TQ, B), 256 threads = 64 queries x 4 channel-groups.
// Thread (qi, cg): owns query qi, v-channels c = 4h+cg (h=0..15).
// Phase A: quad computes 64 scores for qi (16 each), online-softmax, writes
//          probabilities to p_s[qi][:] (warp-local -> only __syncwarp needed).
// Phase B: PV with packed f32x2 FMA; p and v read from shared (no SHFL).
// ---------------------------------------------------------------------------
__global__ __launch_bounds__(256, 2) void attn_kernel(
    const float* __restrict__ x,
    const float* __restrict__ gamma_p,
    float* __restrict__ out)
{
    __shared__ __align__(16) float k_s[CK][TK];   // [kk][j]
    __shared__ __align__(16) float v_s[C][68];    // [c][j], pad -> conflict-free
    __shared__ __align__(16) float p_s[TQ][68];   // [qi][j], pad

    int tid = threadIdx.x;
    int qi = tid >> 2, cg = tid & 3;
    int b = blockIdx.y;
    int qglob = blockIdx.x * TQ + qi;

    // q for this query (constant across tiles), pre-packed for fma2
    ull q2[CK];
#pragma unroll
    for (int kk = 0; kk < CK; kk++) {
        float qv = g_q[(b * CK + kk) * N + qglob];
        q2[kk] = pack2(qv, qv);
    }

    float m = -3.0e38f, l = 0.f;
    ull acc[16];   // f32x2 partial sums (even-j / odd-j), per owned channel
#pragma unroll
    for (int h = 0; h < 16; h++) acc[h] = 0ull;

    const float* kbase = g_k + b * CK * N;
    const float* vbase = g_v + b * C * N;

    for (int kt = 0; kt < NT; kt++) {
        int j0 = kt * TK;
        __syncthreads();   // previous tile's phase B done before overwrite
        for (int idx = tid; idx < CK * TK; idx += 256) {
            int kk = idx >> 6, j = idx & 63;
            k_s[kk][j] = kbase[kk * N + j0 + j];
        }
        for (int idx = tid; idx < C * TK; idx += 256) {
            int c = idx >> 6, j = idx & 63;
            v_s[c][j] = vbase[c * N + j0 + j];
        }
        __syncthreads();

        // ---- Phase A: scores for own 16 j's (j = cg*16 + jj) ----
        ull s2[8];
#pragma unroll
        for (int p = 0; p < 8; p++) s2[p] = 0ull;
#pragma unroll
        for (int kk = 0; kk < CK; kk++) {
            const ull* krow = (const ull*)&k_s[kk][cg * 16];
#pragma unroll
            for (int p = 0; p < 8; p++) s2[p] = fma2(krow[p], q2[kk], s2[p]);
        }
        float s[16];
#pragma unroll
        for (int p = 0; p < 8; p++) unpack2(s2[p], s[2 * p], s[2 * p + 1]);

        float tmax = s[0];
#pragma unroll
        for (int jj = 1; jj < 16; jj++) tmax = fmaxf(tmax, s[jj]);
        tmax = fmaxf(tmax, __shfl_xor_sync(0xffffffffu, tmax, 1));
        tmax = fmaxf(tmax, __shfl_xor_sync(0xffffffffu, tmax, 2));
        float m_new = fmaxf(m, tmax);
        float alpha = __expf(m - m_new);

        float lsum = 0.f;
        float4* prow4 = (float4*)&p_s[qi][cg * 16];
#pragma unroll
        for (int g = 0; g < 4; g++) {
            float p0 = __expf(s[4 * g + 0] - m_new);
            float p1 = __expf(s[4 * g + 1] - m_new);
            float p2 = __expf(s[4 * g + 2] - m_new);
            float p3 = __expf(s[4 * g + 3] - m_new);
            lsum += (p0 + p1) + (p2 + p3);
            prow4[g] = make_float4(p0, p1, p2, p3);
        }
        lsum += __shfl_xor_sync(0xffffffffu, lsum, 1);
        lsum += __shfl_xor_sync(0xffffffffu, lsum, 2);
        l = l * alpha + lsum;
        m = m_new;

        __syncwarp();   // p_s[qi][:] written by this quad's warp only

        // ---- Phase B: PV accumulation ----
        ull alpha2 = pack2(alpha, alpha);
#pragma unroll
        for (int h = 0; h < 16; h++) acc[h] = mul2(acc[h], alpha2);

        const float* prow = &p_s[qi][0];
        const char* vcol = (const char*)&v_s[0][0] + (size_t)cg * (68 * 4);
#pragma unroll 2
        for (int j4 = 0; j4 < TK; j4 += 4) {
            float4 p4 = *(const float4*)(prow + j4);
            ull pj01 = pack2(p4.x, p4.y);
            ull pj23 = pack2(p4.z, p4.w);
            const char* vp = vcol + j4 * 4;
#pragma unroll
            for (int h = 0; h < 16; h++) {
                ulonglong2 v2 = *(const ulonglong2*)(vp + (size_t)h * (4 * 68 * 4));
                acc[h] = fma2(v2.x, pj01, acc[h]);
                acc[h] = fma2(v2.y, pj23, acc[h]);
            }
        }
    }

    // Epilogue: out = gamma * (acc/l) + x
    float inv_l = 1.f / l;
    float gamma = gamma_p[0];
#pragma unroll
    for (int h = 0; h < 16; h++) {
        float lo, hi;
        unpack2(acc[h], lo, hi);
        float a = (lo + hi) * inv_l;
        int c = 4 * h + cg;
        size_t oidx = (size_t)(b * C + c) * N + qglob;
        out[oidx] = gamma * a + x[oidx];
    }
}

// ---------------------------------------------------------------------------
extern "C" void kernel_launch(void* const* d_in, const int* in_sizes, int n_in,
                              void* d_out, int out_size)
{
    const float* x     = (const float*)d_in[0];
    const float* wq    = (const float*)d_in[1];
    const float* bq    = (const float*)d_in[2];
    const float* wk    = (const float*)d_in[3];
    const float* bk    = (const float*)d_in[4];
    const float* wv    = (const float*)d_in[5];
    const float* bv    = (const float*)d_in[6];
    const float* gamma = (const float*)d_in[7];
    float* out = (float*)d_out;

    qkv_kernel<<<64, 256>>>(x, wq, bq, wk, bk, wv, bv);
    dim3 grid(N / TQ, B);
    attn_kernel<<<grid, 256>>>(x, gamma, out);
}

// round 4
// speedup vs baseline: 2.1046x; 1.8079x over previous
#include <cuda_runtime.h>
#include <cstdint>

typedef unsigned long long ull;

#define DEV_INLINE __device__ __forceinline__

DEV_INLINE ull pack2(float lo, float hi) {
    ull r; asm("mov.b64 %0,{%1,%2};" : "=l"(r) : "f"(lo), "f"(hi)); return r;
}
DEV_INLINE void unpack2(ull v, float& lo, float& hi) {
    asm("mov.b64 {%0,%1},%2;" : "=f"(lo), "=f"(hi) : "l"(v));
}
DEV_INLINE ull fma2(ull a, ull b, ull c) {
    ull d; asm("fma.rn.f32x2 %0,%1,%2,%3;" : "=l"(d) : "l"(a), "l"(b), "l"(c)); return d;
}
DEV_INLINE ull mul2(ull a, ull b) {
    ull d; asm("mul.rn.f32x2 %0,%1,%2;" : "=l"(d) : "l"(a), "l"(b)); return d;
}

constexpr int B  = 4;
constexpr int C  = 64;
constexpr int CK = 8;
constexpr int N  = 4096;
constexpr int TQ = 128;  // queries per block
constexpr int TK = 64;   // keys per tile
constexpr int NT = N / TK;

// shared layout (dynamic): k_s[8][64], v_s[64][68] (j-major, padded), p_s[64][128]
constexpr int KS_ELEMS = CK * TK;            // 512
constexpr int VS_STRIDE = 68;                // floats per j-row
constexpr int VS_ELEMS = TK * VS_STRIDE;     // 4352
constexpr int PS_ELEMS = TK * TQ;            // 8192
constexpr int SMEM_BYTES = (KS_ELEMS + VS_ELEMS + PS_ELEMS) * 4;  // 52224

// Scratch (device globals: allocation-guard safe)
__device__ float g_q[B * CK * N];
__device__ float g_k[B * CK * N];
__device__ float g_v[B * C * N];

// ---------------------------------------------------------------------------
// QKV projection (unchanged)
// ---------------------------------------------------------------------------
__global__ __launch_bounds__(256, 1) void qkv_kernel(
    const float* __restrict__ x,
    const float* __restrict__ wq, const float* __restrict__ bq,
    const float* __restrict__ wk, const float* __restrict__ bk,
    const float* __restrict__ wv, const float* __restrict__ bv)
{
    __shared__ float s_wq[CK * C], s_wk[CK * C], s_wv[C * C];
    __shared__ float s_b[2 * CK + C];
    int tid = threadIdx.x;
    for (int i = tid; i < CK * C; i += 256) { s_wq[i] = wq[i]; s_wk[i] = wk[i]; }
    for (int i = tid; i < C * C; i += 256) s_wv[i] = wv[i];
    if (tid < CK) s_b[tid] = bq[tid];
    else if (tid < 2 * CK) s_b[tid] = bk[tid - CK];
    else if (tid < 2 * CK + C) s_b[tid] = bv[tid - 2 * CK];
    __syncthreads();

    int b = blockIdx.x >> 4;
    int n = ((blockIdx.x & 15) << 8) + tid;
    const float* xb = x + (size_t)b * C * N + n;

    float aq[CK], ak[CK];
#pragma unroll
    for (int o = 0; o < CK; o++) { aq[o] = 0.f; ak[o] = 0.f; }
    for (int c = 0; c < C; c++) {
        float xc = xb[(size_t)c * N];
#pragma unroll
        for (int o = 0; o < CK; o++) {
            aq[o] += s_wq[o * C + c] * xc;
            ak[o] += s_wk[o * C + c] * xc;
        }
    }
#pragma unroll
    for (int o = 0; o < CK; o++) {
        g_q[(b * CK + o) * N + n] = aq[o] + s_b[o];
        g_k[(b * CK + o) * N + n] = ak[o] + s_b[CK + o];
    }

    float av[C];
#pragma unroll
    for (int o = 0; o < C; o++) av[o] = 0.f;
    for (int c = 0; c < C; c++) {
        float xc = xb[(size_t)c * N];
#pragma unroll
        for (int o = 0; o < C; o++) av[o] += s_wv[o * C + c] * xc;
    }
#pragma unroll
    for (int o = 0; o < C; o++) g_v[(b * C + o) * N + n] = av[o] + s_b[2 * CK + o];
}

// ---------------------------------------------------------------------------
// Flash attention, register-blocked.
// grid (N/TQ=32, B). 256 threads.
// QK role: sq=tid>>3 (4 queries q=4sq+qq), sj=tid&7 (8 keys j=8sj+jj).
// PV role: pq=tid>>3 (== sq: same 4 queries -> alpha/l stay in regs),
//          pc=tid&7 (8 channels c=8pc+cc).
// p_s[j][q] with XOR-swizzled float4 blocks: block_store = sq ^ ((j>>3)<<2).
// v_s[j][c] (transposed at staging) stride 68.
// ---------------------------------------------------------------------------
__global__ __launch_bounds__(256, 1) void attn_kernel(
    const float* __restrict__ x,
    const float* __restrict__ gamma_p,
    float* __restrict__ out)
{
    extern __shared__ float smem[];
    float* k_s = smem;                 // [8][64]
    float* v_s = smem + KS_ELEMS;      // [64][68]
    float* p_s = v_s + VS_ELEMS;       // [64][128]

    int tid = threadIdx.x;
    int sq = tid >> 3;     // 0..31  (q-group, shared by both roles)
    int sj = tid & 7;      // 0..7   (QK key-group)
    int pc = tid & 7;      // 0..7   (PV channel-group)
    int b = blockIdx.y;
    int qbase = blockIdx.x * TQ;
    int q0 = qbase + sq * 4;

    // q for 4 owned queries x 8 channels, cached in registers
    float q_r[4][CK];
#pragma unroll
    for (int qq = 0; qq < 4; qq++)
#pragma unroll
        for (int ch = 0; ch < CK; ch++)
            q_r[qq][ch] = g_q[(b * CK + ch) * N + q0 + qq];

    float m_r[4], l_r[4];
#pragma unroll
    for (int qq = 0; qq < 4; qq++) { m_r[qq] = -3.0e38f; l_r[qq] = 0.f; }

    ull acc2[4][4];   // [c-pair within 8c][qq]
#pragma unroll
    for (int cp = 0; cp < 4; cp++)
#pragma unroll
        for (int qq = 0; qq < 4; qq++) acc2[cp][qq] = 0ull;

    const float* kbase = g_k + b * CK * N;
    const float* vbase = g_v + b * C * N;

    // v staging role: tc = tid>>4 (0..15) -> channels 4tc..4tc+3; jq = tid&15
    int tc = tid >> 4, jq = tid & 15;

    for (int kt = 0; kt < NT; kt++) {
        int j0 = kt * TK;
        __syncthreads();   // previous PV done before restaging

        // stage k_s[ch][j]
        if (tid < 128) {
            int ch = tid >> 4, j4 = (tid & 15) * 4;
            *(float4*)&k_s[ch * TK + j4] =
                *(const float4*)&kbase[ch * N + j0 + j4];
        }
        // stage v_s[j][c] via register transpose
        {
            const float* src = vbase + (size_t)(4 * tc) * N + j0 + 4 * jq;
            float4 r0 = *(const float4*)(src);
            float4 r1 = *(const float4*)(src + N);
            float4 r2 = *(const float4*)(src + 2 * N);
            float4 r3 = *(const float4*)(src + 3 * N);
            int jb = 4 * jq;
            *(float4*)&v_s[(jb + 0) * VS_STRIDE + 4 * tc] = make_float4(r0.x, r1.x, r2.x, r3.x);
            *(float4*)&v_s[(jb + 1) * VS_STRIDE + 4 * tc] = make_float4(r0.y, r1.y, r2.y, r3.y);
            *(float4*)&v_s[(jb + 2) * VS_STRIDE + 4 * tc] = make_float4(r0.z, r1.z, r2.z, r3.z);
            *(float4*)&v_s[(jb + 3) * VS_STRIDE + 4 * tc] = make_float4(r0.w, r1.w, r2.w, r3.w);
        }
        __syncthreads();

        // ---- QK phase: scores for 4q x 8j ----
        ull s2[4][4];
#pragma unroll
        for (int qq = 0; qq < 4; qq++)
#pragma unroll
            for (int jp = 0; jp < 4; jp++) s2[qq][jp] = 0ull;
#pragma unroll
        for (int ch = 0; ch < CK; ch++) {
            const float* kr = &k_s[ch * TK + sj * 8];
            ulonglong2 kA = *(const ulonglong2*)kr;
            ulonglong2 kB = *(const ulonglong2*)(kr + 4);
            ull kp[4] = {kA.x, kA.y, kB.x, kB.y};
#pragma unroll
            for (int qq = 0; qq < 4; qq++) {
                ull qd = pack2(q_r[qq][ch], q_r[qq][ch]);
#pragma unroll
                for (int jp = 0; jp < 4; jp++)
                    s2[qq][jp] = fma2(kp[jp], qd, s2[qq][jp]);
            }
        }
        float sv[4][8];
#pragma unroll
        for (int qq = 0; qq < 4; qq++)
#pragma unroll
            for (int jp = 0; jp < 4; jp++)
                unpack2(s2[qq][jp], sv[qq][2 * jp], sv[qq][2 * jp + 1]);

        // row max across 64 j (local 8 + shfl over sj lanes)
        float alpha[4];
#pragma unroll
        for (int qq = 0; qq < 4; qq++) {
            float mx = sv[qq][0];
#pragma unroll
            for (int jj = 1; jj < 8; jj++) mx = fmaxf(mx, sv[qq][jj]);
            mx = fmaxf(mx, __shfl_xor_sync(0xffffffffu, mx, 1));
            mx = fmaxf(mx, __shfl_xor_sync(0xffffffffu, mx, 2));
            mx = fmaxf(mx, __shfl_xor_sync(0xffffffffu, mx, 4));
            float m_new = fmaxf(m_r[qq], mx);
            alpha[qq] = __expf(m_r[qq] - m_new);
            m_r[qq] = m_new;
        }
        // exp + row sum
        float e[4][8];
#pragma unroll
        for (int qq = 0; qq < 4; qq++) {
            float ls = 0.f;
#pragma unroll
            for (int jj = 0; jj < 8; jj++) {
                e[qq][jj] = __expf(sv[qq][jj] - m_r[qq]);
                ls += e[qq][jj];
            }
            ls += __shfl_xor_sync(0xffffffffu, ls, 1);
            ls += __shfl_xor_sync(0xffffffffu, ls, 2);
            ls += __shfl_xor_sync(0xffffffffu, ls, 4);
            l_r[qq] = l_r[qq] * alpha[qq] + ls;
        }
        // write p_s[j][4sq..4sq+3], swizzled block = sq ^ (sj<<2)
        {
            int bsw = (sq ^ (sj << 2)) << 2;
#pragma unroll
            for (int jj = 0; jj < 8; jj++) {
                int j = sj * 8 + jj;
                *(float4*)&p_s[j * TQ + bsw] =
                    make_float4(e[0][jj], e[1][jj], e[2][jj], e[3][jj]);
            }
        }
        __syncthreads();

        // ---- PV phase: 8c x 4q per thread ----
#pragma unroll
        for (int qq = 0; qq < 4; qq++) {
            ull a2 = pack2(alpha[qq], alpha[qq]);
#pragma unroll
            for (int cp = 0; cp < 4; cp++)
                acc2[cp][qq] = mul2(acc2[cp][qq], a2);
        }
#pragma unroll 4
        for (int j = 0; j < TK; j++) {
            int sjr = (j >> 3) << 2;
            const float4 p4 = *(const float4*)&p_s[j * TQ + ((sq ^ sjr) << 2)];
            ull pd[4] = {pack2(p4.x, p4.x), pack2(p4.y, p4.y),
                         pack2(p4.z, p4.z), pack2(p4.w, p4.w)};
            const float* vr = &v_s[j * VS_STRIDE + pc * 8];
            ulonglong2 vA = *(const ulonglong2*)vr;
            ulonglong2 vB = *(const ulonglong2*)(vr + 4);
            ull vp[4] = {vA.x, vA.y, vB.x, vB.y};
#pragma unroll
            for (int qq = 0; qq < 4; qq++)
#pragma unroll
                for (int cp = 0; cp < 4; cp++)
                    acc2[cp][qq] = fma2(vp[cp], pd[qq], acc2[cp][qq]);
        }
    }

    // ---- epilogue: out = gamma * acc/l + x ----
    float gamma = gamma_p[0];
    float inv_l[4];
#pragma unroll
    for (int qq = 0; qq < 4; qq++) inv_l[qq] = 1.f / l_r[qq];

#pragma unroll
    for (int cp = 0; cp < 4; cp++) {
        float ev[4], ov[4];
#pragma unroll
        for (int qq = 0; qq < 4; qq++) unpack2(acc2[cp][qq], ev[qq], ov[qq]);
        int c_even = pc * 8 + 2 * cp;
        size_t base_e = (size_t)(b * C + c_even) * N + q0;
        size_t base_o = base_e + N;
        float4 xe = *(const float4*)&x[base_e];
        float4 xo = *(const float4*)&x[base_o];
        float4 oe = make_float4(gamma * ev[0] * inv_l[0] + xe.x,
                                gamma * ev[1] * inv_l[1] + xe.y,
                                gamma * ev[2] * inv_l[2] + xe.z,
                                gamma * ev[3] * inv_l[3] + xe.w);
        float4 oo = make_float4(gamma * ov[0] * inv_l[0] + xo.x,
                                gamma * ov[1] * inv_l[1] + xo.y,
                                gamma * ov[2] * inv_l[2] + xo.z,
                                gamma * ov[3] * inv_l[3] + xo.w);
        *(float4*)&out[base_e] = oe;
        *(float4*)&out[base_o] = oo;
    }
}

// ---------------------------------------------------------------------------
extern "C" void kernel_launch(void* const* d_in, const int* in_sizes, int n_in,
                              void* d_out, int out_size)
{
    const float* x     = (const float*)d_in[0];
    const float* wq    = (const float*)d_in[1];
    const float* bq    = (const float*)d_in[2];
    const float* wk    = (const float*)d_in[3];
    const float* bk    = (const float*)d_in[4];
    const float* wv    = (const float*)d_in[5];
    const float* bv    = (const float*)d_in[6];
    const float* gamma = (const float*)d_in[7];
    float* out = (float*)d_out;

    cudaFuncSetAttribute(attn_kernel,
                         cudaFuncAttributeMaxDynamicSharedMemorySize, SMEM_BYTES);

    qkv_kernel<<<64, 256>>>(x, wq, bq, wk, bk, wv, bv);
    dim3 grid(N / TQ, B);
    attn_kernel<<<grid, 256, SMEM_BYTES>>>(x, gamma, out);
}

// round 6
// speedup vs baseline: 10.5681x; 5.0215x over previous
#include <cuda_runtime.h>
#include <cuda_fp16.h>
#include <cstdint>

#define DEV_INLINE __device__ __forceinline__

constexpr int B  = 4;
constexpr int C  = 64;
constexpr int CK = 8;
constexpr int N  = 4096;
constexpr int TQ = 128;  // queries per block (8 warps x 16)
constexpr int TK = 64;   // keys per tile
constexpr int NT = N / TK;
constexpr float LOG2E = 1.4426950408889634f;

// Scratch (device globals: allocation-guard safe)
__device__ float g_q[B * CK * N];   // stored pre-scaled by log2(e)
__device__ float g_k[B * CK * N];
__device__ float g_v[B * C * N];

DEV_INLINE uint32_t pack_h2(float lo, float hi) {
    uint32_t r;
    asm("cvt.rn.f16x2.f32 %0, %1, %2;" : "=r"(r) : "f"(hi), "f"(lo));
    return r;
}
DEV_INLINE float ex2f(float x) {
    float r; asm("ex2.approx.f32 %0, %1;" : "=f"(r) : "f"(x)); return r;
}

#define MMA_K8(d, a0, a1, b0) \
    asm volatile("mma.sync.aligned.m16n8k8.row.col.f32.f16.f16.f32 " \
        "{%0,%1,%2,%3}, {%4,%5}, {%6}, {%0,%1,%2,%3};" \
        : "+f"((d)[0]), "+f"((d)[1]), "+f"((d)[2]), "+f"((d)[3]) \
        : "r"(a0), "r"(a1), "r"(b0))

#define MMA_K16(d, a0, a1, a2, a3, b0, b1) \
    asm volatile("mma.sync.aligned.m16n8k16.row.col.f32.f16.f16.f32 " \
        "{%0,%1,%2,%3}, {%4,%5,%6,%7}, {%8,%9}, {%0,%1,%2,%3};" \
        : "+f"((d)[0]), "+f"((d)[1]), "+f"((d)[2]), "+f"((d)[3]) \
        : "r"(a0), "r"(a1), "r"(a2), "r"(a3), "r"(b0), "r"(b1))

// ---------------------------------------------------------------------------
// QKV projection. q additionally scaled by log2(e) so attention uses ex2.
// ---------------------------------------------------------------------------
__global__ __launch_bounds__(256, 1) void qkv_kernel(
    const float* __restrict__ x,
    const float* __restrict__ wq, const float* __restrict__ bq,
    const float* __restrict__ wk, const float* __restrict__ bk,
    const float* __restrict__ wv, const float* __restrict__ bv)
{
    __shared__ float s_wq[CK * C], s_wk[CK * C], s_wv[C * C];
    __shared__ float s_b[2 * CK + C];
    int tid = threadIdx.x;
    for (int i = tid; i < CK * C; i += 256) { s_wq[i] = wq[i]; s_wk[i] = wk[i]; }
    for (int i = tid; i < C * C; i += 256) s_wv[i] = wv[i];
    if (tid < CK) s_b[tid] = bq[tid];
    else if (tid < 2 * CK) s_b[tid] = bk[tid - CK];
    else if (tid < 2 * CK + C) s_b[tid] = bv[tid - 2 * CK];
    __syncthreads();

    int b = blockIdx.x >> 4;
    int n = ((blockIdx.x & 15) << 8) + tid;
    const float* xb = x + (size_t)b * C * N + n;

    float aq[CK], ak[CK];
#pragma unroll
    for (int o = 0; o < CK; o++) { aq[o] = 0.f; ak[o] = 0.f; }
    for (int c = 0; c < C; c++) {
        float xc = xb[(size_t)c * N];
#pragma unroll
        for (int o = 0; o < CK; o++) {
            aq[o] += s_wq[o * C + c] * xc;
            ak[o] += s_wk[o * C + c] * xc;
        }
    }
#pragma unroll
    for (int o = 0; o < CK; o++) {
        g_q[(b * CK + o) * N + n] = (aq[o] + s_b[o]) * LOG2E;
        g_k[(b * CK + o) * N + n] = ak[o] + s_b[CK + o];
    }

    float av[C];
#pragma unroll
    for (int o = 0; o < C; o++) av[o] = 0.f;
    for (int c = 0; c < C; c++) {
        float xc = xb[(size_t)c * N];
#pragma unroll
        for (int o = 0; o < C; o++) av[o] += s_wv[o * C + c] * xc;
    }
#pragma unroll
    for (int o = 0; o < C; o++) g_v[(b * C + o) * N + n] = av[o] + s_b[2 * CK + o];
}

// ---------------------------------------------------------------------------
// mma.sync fp16 flash attention.
// grid (N/TQ=32, B), 256 threads = 8 warps, warp w owns queries qbase+16w..+15.
// smem (all half2-as-u32, conflict-free layouts):
//   q_s[q][c2]    : [128][4]   pack(Q[2c2][q],   Q[2c2+1][q])
//   k_s[c2][j]    : [4][72]    pack(K[2c2][j],   K[2c2+1][j])
//   v_s[c][j2]    : [64][36]   pack(V[2j2][c],   V[2j2+1][c])
// QK: 8x m16n8k8 (A=Q regs, B=K LDS). PV: 4x8 m16n8k16, A-frags are the
// exp'ed QK D-frags packed in place (FA2 property) — no shuffle, no smem.
// ---------------------------------------------------------------------------
__global__ __launch_bounds__(256, 1) void attn_kernel(
    const float* __restrict__ x,
    const float* __restrict__ gamma_p,
    float* __restrict__ out)
{
    __shared__ uint32_t q_s[128 * 4];
    __shared__ uint32_t k_s[4 * 72];
    __shared__ uint32_t v_s[64 * 36];

    int tid = threadIdx.x;
    int w = tid >> 5, lane = tid & 31, t = lane & 3, r = lane >> 2;
    int b = blockIdx.y, qbase = blockIdx.x * TQ;

    const float* qbp = g_q + b * CK * N;
    const float* kbp = g_k + b * CK * N;
    const float* vbp = g_v + b * C * N;

    // stage Q once (512 slots / 256 threads)
    {
        int qs = tid >> 2, c2 = tid & 3;
#pragma unroll
        for (int i = 0; i < 2; i++) {
            int q = qs + 64 * i;
            float f0 = qbp[(2 * c2) * N + qbase + q];
            float f1 = qbp[(2 * c2 + 1) * N + qbase + q];
            q_s[q * 4 + c2] = pack_h2(f0, f1);
        }
    }

    // prefetch roles
    int c2k = tid >> 6, jk = tid & 63;
    const float* kp0 = kbp + (size_t)(2 * c2k) * N + jk;
    const float* kp1 = kbp + (size_t)(2 * c2k + 1) * N + jk;
    float kf0, kf1;
    float2 vf[8];

    // prefetch tile 0
    kf0 = kp0[0]; kf1 = kp1[0];
#pragma unroll
    for (int i = 0; i < 8; i++)
        vf[i] = *(const float2*)&vbp[(size_t)(w + 8 * i) * N + 2 * lane];

    __syncthreads();
    uint32_t qa0 = q_s[(w * 16 + r) * 4 + t];
    uint32_t qa1 = q_s[(w * 16 + r + 8) * 4 + t];

    float o[8][4];
#pragma unroll
    for (int n = 0; n < 8; n++)
#pragma unroll
        for (int k = 0; k < 4; k++) o[n][k] = 0.f;
    float l0 = 0.f, l1 = 0.f, m0 = -1e30f, m1 = -1e30f;

    for (int kt = 0; kt < NT; kt++) {
        // store prefetched tile
        k_s[c2k * 72 + jk] = pack_h2(kf0, kf1);
#pragma unroll
        for (int i = 0; i < 8; i++)
            v_s[(w + 8 * i) * 36 + lane] = pack_h2(vf[i].x, vf[i].y);
        __syncthreads();

        // prefetch next tile (overlaps with compute)
        if (kt + 1 < NT) {
            int j0n = (kt + 1) * TK;
            kf0 = kp0[j0n]; kf1 = kp1[j0n];
#pragma unroll
            for (int i = 0; i < 8; i++)
                vf[i] = *(const float2*)&vbp[(size_t)(w + 8 * i) * N + j0n + 2 * lane];
        }

        // ---- QK: S[16q x 64j] in 8 D-frags ----
        float s[8][4];
#pragma unroll
        for (int jt = 0; jt < 8; jt++) {
            s[jt][0] = 0.f; s[jt][1] = 0.f; s[jt][2] = 0.f; s[jt][3] = 0.f;
            uint32_t kb = k_s[t * 72 + jt * 8 + r];
            MMA_K8(s[jt], qa0, qa1, kb);
        }

        // ---- online softmax (log2 domain) ----
        float tm0 = -1e30f, tm1 = -1e30f;
#pragma unroll
        for (int jt = 0; jt < 8; jt++) {
            tm0 = fmaxf(tm0, fmaxf(s[jt][0], s[jt][1]));
            tm1 = fmaxf(tm1, fmaxf(s[jt][2], s[jt][3]));
        }
        tm0 = fmaxf(tm0, __shfl_xor_sync(0xffffffffu, tm0, 1));
        tm0 = fmaxf(tm0, __shfl_xor_sync(0xffffffffu, tm0, 2));
        tm1 = fmaxf(tm1, __shfl_xor_sync(0xffffffffu, tm1, 1));
        tm1 = fmaxf(tm1, __shfl_xor_sync(0xffffffffu, tm1, 2));
        float mn0 = fmaxf(m0, tm0), mn1 = fmaxf(m1, tm1);
        float al0 = ex2f(m0 - mn0), al1 = ex2f(m1 - mn1);
        m0 = mn0; m1 = mn1;

        float sum0 = 0.f, sum1 = 0.f;
#pragma unroll
        for (int jt = 0; jt < 8; jt++) {
            s[jt][0] = ex2f(s[jt][0] - mn0);
            s[jt][1] = ex2f(s[jt][1] - mn0);
            s[jt][2] = ex2f(s[jt][2] - mn1);
            s[jt][3] = ex2f(s[jt][3] - mn1);
            sum0 += s[jt][0] + s[jt][1];
            sum1 += s[jt][2] + s[jt][3];
        }
        sum0 += __shfl_xor_sync(0xffffffffu, sum0, 1);
        sum0 += __shfl_xor_sync(0xffffffffu, sum0, 2);
        sum1 += __shfl_xor_sync(0xffffffffu, sum1, 1);
        sum1 += __shfl_xor_sync(0xffffffffu, sum1, 2);
        l0 = l0 * al0 + sum0;
        l1 = l1 * al1 + sum1;

        // rescale O by alpha
#pragma unroll
        for (int n = 0; n < 8; n++) {
            o[n][0] *= al0; o[n][1] *= al0;
            o[n][2] *= al1; o[n][3] *= al1;
        }

        // pack P into PV A-frags (in-register, FA2 layout identity)
        uint32_t pa[4][4];
#pragma unroll
        for (int s4 = 0; s4 < 4; s4++) {
            pa[s4][0] = pack_h2(s[2 * s4][0],     s[2 * s4][1]);
            pa[s4][1] = pack_h2(s[2 * s4][2],     s[2 * s4][3]);
            pa[s4][2] = pack_h2(s[2 * s4 + 1][0], s[2 * s4 + 1][1]);
            pa[s4][3] = pack_h2(s[2 * s4 + 1][2], s[2 * s4 + 1][3]);
        }

        // ---- PV: O[16q x 64c] += P @ V ----
#pragma unroll
        for (int s4 = 0; s4 < 4; s4++) {
#pragma unroll
            for (int n = 0; n < 8; n++) {
                uint32_t b0 = v_s[(8 * n + r) * 36 + 8 * s4 + t];
                uint32_t b1 = v_s[(8 * n + r) * 36 + 8 * s4 + 4 + t];
                MMA_K16(o[n], pa[s4][0], pa[s4][1], pa[s4][2], pa[s4][3], b0, b1);
            }
        }
        __syncthreads();   // all reads done before next tile's STS
    }

    // ---- epilogue: out = gamma * O/l + x ----
    float invl0 = 1.f / l0, invl1 = 1.f / l1;
    float gm = gamma_p[0];
    int q0 = qbase + w * 16 + r;
#pragma unroll
    for (int n = 0; n < 8; n++) {
        int c = 8 * n + 2 * t;
        size_t i00 = (size_t)(b * C + c) * N + q0;
        size_t i01 = i00 + N;   // c+1
        out[i00]     = gm * o[n][0] * invl0 + x[i00];
        out[i01]     = gm * o[n][1] * invl0 + x[i01];
        out[i00 + 8] = gm * o[n][2] * invl1 + x[i00 + 8];
        out[i01 + 8] = gm * o[n][3] * invl1 + x[i01 + 8];
    }
}

// ---------------------------------------------------------------------------
extern "C" void kernel_launch(void* const* d_in, const int* in_sizes, int n_in,
                              void* d_out, int out_size)
{
    const float* x     = (const float*)d_in[0];
    const float* wq    = (const float*)d_in[1];
    const float* bq    = (const float*)d_in[2];
    const float* wk    = (const float*)d_in[3];
    const float* bk    = (const float*)d_in[4];
    const float* wv    = (const float*)d_in[5];
    const float* bv    = (const float*)d_in[6];
    const float* gamma = (const float*)d_in[7];
    float* out = (float*)d_out;

    qkv_kernel<<<64, 256>>>(x, wq, bq, wk, bk, wv, bv);
    dim3 grid(N / TQ, B);
    attn_kernel<<<grid, 256>>>(x, gamma, out);
}

// round 9
// speedup vs baseline: 13.6035x; 1.2872x over previous
#include <cuda_runtime.h>
#include <cuda_fp16.h>
#include <cstdint>

#define DEV_INLINE __device__ __forceinline__

constexpr int B  = 4;
constexpr int C  = 64;
constexpr int CK = 8;
constexpr int N  = 4096;
constexpr int TQ = 64;   // queries per block (4 warps x 16)
constexpr int TK = 64;   // keys per tile
constexpr int NT = N / TK;
constexpr float LOG2E = 1.4426950408889634f;

// fp16 scratch, layouts chosen so attention staging is a raw byte copy:
//   g_q/g_k: [b][n][c]  (8 half = 16B per n; u32 at [n*4+t] = ch pair 2t,2t+1)
//   g_v:     [b][c][n]  (u32 at j2 = key pair 2j2,2j2+1)
__device__ __half g_q[B * N * CK];
__device__ __half g_k[B * N * CK];
__device__ __half g_v[B * C * N];

DEV_INLINE uint32_t pack_h2(float lo, float hi) {
    uint32_t r;
    asm("cvt.rn.f16x2.f32 %0, %1, %2;" : "=r"(r) : "f"(hi), "f"(lo));
    return r;
}
DEV_INLINE float ex2f(float x) {
    float r; asm("ex2.approx.f32 %0, %1;" : "=f"(r) : "f"(x)); return r;
}
DEV_INLINE uint32_t h2ex2(uint32_t a) {
    uint32_t d; asm("ex2.approx.f16x2 %0, %1;" : "=r"(d) : "r"(a)); return d;
}
DEV_INLINE uint32_t h2add(uint32_t a, uint32_t b) {
    uint32_t d; asm("add.rn.f16x2 %0, %1, %2;" : "=r"(d) : "r"(a), "r"(b)); return d;
}
DEV_INLINE uint32_t smem_u32(const void* p) {
    uint32_t a;
    asm("{ .reg .u64 t; cvta.to.shared.u64 t, %1; cvt.u32.u64 %0, t; }"
        : "=r"(a) : "l"(p));
    return a;
}
DEV_INLINE void cp16(uint32_t dst, const void* src) {
    asm volatile("cp.async.ca.shared.global [%0], [%1], 16;"
                 :: "r"(dst), "l"(src) : "memory");
}
#define CP_COMMIT() asm volatile("cp.async.commit_group;" ::: "memory")
#define CP_WAIT1()  asm volatile("cp.async.wait_group 1;" ::: "memory")
#define CP_WAIT0()  asm volatile("cp.async.wait_group 0;" ::: "memory")

#define MMA_K8(d, a0, a1, b0) \
    asm volatile("mma.sync.aligned.m16n8k8.row.col.f32.f16.f16.f32 " \
        "{%0,%1,%2,%3}, {%4,%5}, {%6}, {%0,%1,%2,%3};" \
        : "+f"((d)[0]), "+f"((d)[1]), "+f"((d)[2]), "+f"((d)[3]) \
        : "r"(a0), "r"(a1), "r"(b0))

#define MMA_K16(d, a0, a1, a2, a3, b0, b1) \
    asm volatile("mma.sync.aligned.m16n8k16.row.col.f32.f16.f16.f32 " \
        "{%0,%1,%2,%3}, {%4,%5,%6,%7}, {%8,%9}, {%0,%1,%2,%3};" \
        : "+f"((d)[0]), "+f"((d)[1]), "+f"((d)[2]), "+f"((d)[3]) \
        : "r"(a0), "r"(a1), "r"(a2), "r"(a3), "r"(b0), "r"(b1))

// ---------------------------------------------------------------------------
// QKV projection -> fp16 scratch. 128 blocks (4 b x 32 n-chunks), 256 thr.
// half h=0: q (scaled by log2e) + v channels 0..31; h=1: k + v 32..63.
// ---------------------------------------------------------------------------
__global__ __launch_bounds__(256, 1) void qkv_kernel(
    const float* __restrict__ x,
    const float* __restrict__ wq, const float* __restrict__ bq,
    const float* __restrict__ wk, const float* __restrict__ bk,
    const float* __restrict__ wv, const float* __restrict__ bv)
{
    __shared__ float s_wq[CK * C], s_wk[CK * C], s_wv[C * C];
    __shared__ float s_b[2 * CK + C];
    int tid = threadIdx.x;
    for (int i = tid; i < CK * C; i += 256) { s_wq[i] = wq[i]; s_wk[i] = wk[i]; }
    for (int i = tid; i < C * C; i += 256) s_wv[i] = wv[i];
    if (tid < CK) s_b[tid] = bq[tid];
    else if (tid < 2 * CK) s_b[tid] = bk[tid - CK];
    else if (tid < 2 * CK + C) s_b[tid] = bv[tid - 2 * CK];
    __syncthreads();

    int b = blockIdx.x >> 5;
    int chunk = blockIdx.x & 31;
    int h = tid >> 7;
    int n = chunk * 128 + (tid & 127);
    const float* xb = x + (size_t)b * C * N + n;

    const float* wqk = h ? s_wk : s_wq;
    const float* bqk = h ? (s_b + CK) : s_b;
    float qscale = h ? 1.0f : LOG2E;
    int vc0 = h * 32;

    float a8[CK], av[32];
#pragma unroll
    for (int o = 0; o < CK; o++) a8[o] = 0.f;
#pragma unroll
    for (int o = 0; o < 32; o++) av[o] = 0.f;

    for (int c = 0; c < C; c++) {
        float xc = xb[(size_t)c * N];
#pragma unroll
        for (int o = 0; o < CK; o++) a8[o] += wqk[o * C + c] * xc;
#pragma unroll
        for (int o = 0; o < 32; o++) av[o] += s_wv[(vc0 + o) * C + c] * xc;
    }

    float f[CK];
#pragma unroll
    for (int o = 0; o < CK; o++) f[o] = (a8[o] + bqk[o]) * qscale;
    uint4 pk = make_uint4(pack_h2(f[0], f[1]), pack_h2(f[2], f[3]),
                          pack_h2(f[4], f[5]), pack_h2(f[6], f[7]));
    uint4* dst = (uint4*)(h ? g_k : g_q) + ((size_t)b * N + n);
    *dst = pk;

#pragma unroll
    for (int o = 0; o < 32; o++)
        g_v[((size_t)b * C + vc0 + o) * N + n] =
            __float2half_rn(av[o] + s_b[2 * CK + vc0 + o]);
}

// ---------------------------------------------------------------------------
// mma.sync fp16 flash attention, online max with lazy rescale, f16x2 exp,
// cp.async triple-buffered K/V staging (1 barrier per tile).
// grid (64, 4), 128 threads = 4 warps x 16 queries.
// smem: k_s[buf][j][c2] (16B rows), v_s[buf][c][j2] (32 data + 4 pad u32).
// ---------------------------------------------------------------------------
__global__ __launch_bounds__(128, 4) void attn_kernel(
    const float* __restrict__ x,
    const float* __restrict__ gamma_p,
    float* __restrict__ out)
{
    __shared__ __align__(16) uint32_t k_s[3][TK * 4];
    __shared__ __align__(16) uint32_t v_s[3][TK * 36];

    int tid = threadIdx.x;
    int w = tid >> 5, lane = tid & 31, t = lane & 3, r = lane >> 2;
    int b = blockIdx.y, qbase = blockIdx.x * TQ;

    const __half* gq = g_q + (size_t)b * N * CK;
    const __half* gk = g_k + (size_t)b * N * CK;
    const __half* gv = g_v + (size_t)b * C * N;

    // Q fragments straight from gmem (no smem staging)
    uint32_t qa0 = ((const uint32_t*)gq)[(qbase + w * 16 + r) * 4 + t];
    uint32_t qa1 = ((const uint32_t*)gq)[(qbase + w * 16 + r + 8) * 4 + t];

    uint32_t ks_base = smem_u32(k_s);
    uint32_t vs_base = smem_u32(v_s);

    // cp.async staging of one tile into buffer `buf`
    auto stage = [&](int buf, int j0) {
        if (tid < 64)
            cp16(ks_base + buf * (TK * 4 * 4) + tid * 16,
                 gk + (size_t)(j0 + tid) * 8);
#pragma unroll
        for (int i = 0; i < 4; i++) {
            int idx = tid + 128 * i;
            int c = idx >> 3, o = idx & 7;
            cp16(vs_base + buf * (TK * 36 * 4) + c * 144 + o * 16,
                 gv + (size_t)c * N + j0 + o * 8);
        }
        CP_COMMIT();
    };

    stage(0, 0);

    float o_[8][4];
#pragma unroll
    for (int n = 0; n < 8; n++)
#pragma unroll
        for (int k = 0; k < 4; k++) o_[n][k] = 0.f;
    float l0 = 0.f, l1 = 0.f, m0 = -1e30f, m1 = -1e30f;

    for (int kt = 0; kt < NT; kt++) {
        int cur = kt % 3;
        if (kt + 1 < NT) {
            stage((kt + 1) % 3, (kt + 1) * TK);
            CP_WAIT1();
        } else {
            CP_WAIT0();
        }
        __syncthreads();

        const uint32_t* kc = k_s[cur];
        const uint32_t* vc = v_s[cur];

        // ---- QK: S[16q x 64j] in 8 D-frags ----
        float s[8][4];
#pragma unroll
        for (int jt = 0; jt < 8; jt++) {
            s[jt][0] = 0.f; s[jt][1] = 0.f; s[jt][2] = 0.f; s[jt][3] = 0.f;
            uint32_t kb = kc[(jt * 8 + r) * 4 + t];
            MMA_K8(s[jt], qa0, qa1, kb);
        }

        // ---- row max (quad-uniform) + lazy rescale ----
        float tm0 = s[0][0], tm1 = s[0][2];
#pragma unroll
        for (int jt = 0; jt < 8; jt++) {
            tm0 = fmaxf(tm0, fmaxf(s[jt][0], s[jt][1]));
            tm1 = fmaxf(tm1, fmaxf(s[jt][2], s[jt][3]));
        }
        tm0 = fmaxf(tm0, __shfl_xor_sync(0xffffffffu, tm0, 1));
        tm0 = fmaxf(tm0, __shfl_xor_sync(0xffffffffu, tm0, 2));
        tm1 = fmaxf(tm1, __shfl_xor_sync(0xffffffffu, tm1, 1));
        tm1 = fmaxf(tm1, __shfl_xor_sync(0xffffffffu, tm1, 2));
        if (tm0 > m0 || tm1 > m1) {
            float mn0 = fmaxf(m0, tm0), mn1 = fmaxf(m1, tm1);
            float al0 = ex2f(m0 - mn0), al1 = ex2f(m1 - mn1);
            l0 *= al0; l1 *= al1;
#pragma unroll
            for (int n = 0; n < 8; n++) {
                o_[n][0] *= al0; o_[n][1] *= al0;
                o_[n][2] *= al1; o_[n][3] *= al1;
            }
            m0 = mn0; m1 = mn1;
        }

        // ---- exp in f16x2 (p <= 1, safe), packed directly as PV A-frags ----
        uint32_t pa[4][4];
#pragma unroll
        for (int s4 = 0; s4 < 4; s4++) {
            pa[s4][0] = h2ex2(pack_h2(s[2 * s4][0] - m0,     s[2 * s4][1] - m0));
            pa[s4][1] = h2ex2(pack_h2(s[2 * s4][2] - m1,     s[2 * s4][3] - m1));
            pa[s4][2] = h2ex2(pack_h2(s[2 * s4 + 1][0] - m0, s[2 * s4 + 1][1] - m0));
            pa[s4][3] = h2ex2(pack_h2(s[2 * s4 + 1][2] - m1, s[2 * s4 + 1][3] - m1));
        }

        // ---- l accumulation via HADD2 trees (values <= 8 per lane: safe) ----
        {
            uint32_t h0 = h2add(h2add(pa[0][0], pa[1][0]), h2add(pa[2][0], pa[3][0]));
            uint32_t h2_ = h2add(h2add(pa[0][2], pa[1][2]), h2add(pa[2][2], pa[3][2]));
            uint32_t hs0 = h2add(h0, h2_);
            uint32_t h1 = h2add(h2add(pa[0][1], pa[1][1]), h2add(pa[2][1], pa[3][1]));
            uint32_t h3 = h2add(h2add(pa[0][3], pa[1][3]), h2add(pa[2][3], pa[3][3]));
            uint32_t hs1 = h2add(h1, h3);
            __half2 v0 = *reinterpret_cast<__half2*>(&hs0);
            __half2 v1 = *reinterpret_cast<__half2*>(&hs1);
            float2 f0 = __half22float2(v0), f1 = __half22float2(v1);
            l0 += f0.x + f0.y;
            l1 += f1.x + f1.y;
        }

        // ---- PV: O += P @ V ----
#pragma unroll
        for (int s4 = 0; s4 < 4; s4++) {
#pragma unroll
            for (int n = 0; n < 8; n++) {
                uint32_t b0 = vc[(8 * n + r) * 36 + 8 * s4 + t];
                uint32_t b1 = vc[(8 * n + r) * 36 + 8 * s4 + 4 + t];
                MMA_K16(o_[n], pa[s4][0], pa[s4][1], pa[s4][2], pa[s4][3], b0, b1);
            }
        }
        __syncthreads();   // all reads of `cur` done before it is re-staged
    }

    // ---- final l reduction across quad lanes ----
    l0 += __shfl_xor_sync(0xffffffffu, l0, 1);
    l0 += __shfl_xor_sync(0xffffffffu, l0, 2);
    l1 += __shfl_xor_sync(0xffffffffu, l1, 1);
    l1 += __shfl_xor_sync(0xffffffffu, l1, 2);

    // ---- epilogue: out = gamma * O/l + x ----
    float invl0 = 1.f / l0, invl1 = 1.f / l1;
    float gm = gamma_p[0];
    int q0 = qbase + w * 16 + r;
#pragma unroll
    for (int n = 0; n < 8; n++) {
        int c = 8 * n + 2 * t;
        size_t i00 = (size_t)(b * C + c) * N + q0;
        size_t i01 = i00 + N;   // c+1
        out[i00]     = gm * o_[n][0] * invl0 + x[i00];
        out[i01]     = gm * o_[n][1] * invl0 + x[i01];
        out[i00 + 8] = gm * o_[n][2] * invl1 + x[i00 + 8];
        out[i01 + 8] = gm * o_[n][3] * invl1 + x[i01 + 8];
    }
}

// ---------------------------------------------------------------------------
extern "C" void kernel_launch(void* const* d_in, const int* in_sizes, int n_in,
                              void* d_out, int out_size)
{
    const float* x     = (const float*)d_in[0];
    const float* wq    = (const float*)d_in[1];
    const float* bq    = (const float*)d_in[2];
    const float* wk    = (const float*)d_in[3];
    const float* bk    = (const float*)d_in[4];
    const float* wv    = (const float*)d_in[5];
    const float* bv    = (const float*)d_in[6];
    const float* gamma = (const float*)d_in[7];
    float* out = (float*)d_out;

    qkv_kernel<<<128, 256>>>(x, wq, bq, wk, bk, wv, bv);
    dim3 grid(N / TQ, B);
    attn_kernel<<<grid, 128>>>(x, gamma, out);
}